// round 14
// baseline (speedup 1.0000x reference)
#include <cuda_runtime.h>
#include <cstdint>

// ---------------------------------------------------------------------------
// MyGraphConv: out = relu([h[:n_dst] || segment_mean(h[edge_src], edge_dst)] @ W.T + b)
//
// R14 plan — 3 linear graph nodes, no streams/events:
//   K1 init   : zero g_cnt/ovf + parallel int32/int64 dtype probe
//   K2 scatter: 1 edge/thread bucket scatter (CAP=128, overflow list)
//   K3 fused  : per CTA (64 dst rows):
//               phase 1: gather + mean into smem Ms[64][128] (fp32)
//               phase 2: full K=256 GEMM (K<128: h from global; K>=128: Ms),
//                        f32x2 FFMA2 inner loop, bias + relu epilogue.
// ---------------------------------------------------------------------------

#define MAX_DST 32768
#define CAP     128
#define MAX_OVF 65536
#define DIMD    128
#define OUTN    128
#define KDIM    256

__device__ int g_cnt[MAX_DST];
__device__ int g_csr[(size_t)MAX_DST * CAP];
__device__ int g_ovf_n;
__device__ int g_ovf[2 * MAX_OVF];
__device__ int g_is64;

// --- K1: zero counters + dtype probe ------------------------------------------
// int64 buffers: every sampled 8B word is a small valid index. int32 buffers:
// an 8B read packs two indices -> exceeds range unless the high half is 0.
// Sample only the first E/2 int64 slots (in-bounds for either dtype).
__global__ void init_kernel(const void* esrc, const void* edst,
                            int E, int n_src, int n_dst) {
    __shared__ int ok;
    if (threadIdx.x == 0) ok = 1;
    __syncthreads();
    int i = blockIdx.x * blockDim.x + threadIdx.x;
    if (i < n_dst) g_cnt[i] = 0;
    if (i == 0) g_ovf_n = 0;
    if (blockIdx.x == 0 && threadIdx.x < 64) {
        int lim = E >> 1;
        if (lim < 1) {
            if (threadIdx.x == 0) atomicAnd(&ok, 0);
        } else {
            int step = (lim > 64) ? (lim / 64) : 1;
            int j = threadIdx.x * step;
            if (j < lim) {
                const unsigned long long* p = (const unsigned long long*)esrc;
                const unsigned long long* q = (const unsigned long long*)edst;
                if (p[j] >= (unsigned long long)n_src ||
                    q[j] >= (unsigned long long)n_dst)
                    atomicAnd(&ok, 0);
            }
        }
    }
    __syncthreads();
    if (blockIdx.x == 0 && threadIdx.x == 0) g_is64 = ok;
}

// --- K2: bucket scatter, 1 edge/thread ------------------------------------------
__global__ void scatter_kernel(const void* __restrict__ esrc,
                               const void* __restrict__ edst, int E) {
    int i = blockIdx.x * blockDim.x + threadIdx.x;
    if (i >= E) return;
    int s, d;
    if (g_is64) {
        s = (int)((const long long*)esrc)[i];
        d = (int)((const long long*)edst)[i];
    } else {
        s = ((const int*)esrc)[i];
        d = ((const int*)edst)[i];
    }
    int pos = atomicAdd(&g_cnt[d], 1);
    if (pos < CAP) {
        g_csr[(size_t)d * CAP + pos] = s;
    } else {
        int o = atomicAdd(&g_ovf_n, 1);
        if (o < MAX_OVF) { g_ovf[2 * o] = d; g_ovf[2 * o + 1] = s; }
    }
}

// --- K3: fused gather + full GEMM + bias + relu ----------------------------------
#define GBM 64
#define GBK 32
#define ZS2_STRIDE 66    // ulonglong stride: 64 + 2 pad
#define WS_STRIDE  132

// Dynamic smem layout (bytes):
#define SM_MS   0                     // float[64][128]          = 32768
#define SM_ZS2  32768                 // ulonglong[32][66]       = 16896
#define SM_WS   (32768 + 16896)       // float[32][132]          = 16896
#define SM_TOT  (32768 + 16896 + 16896)

union F4U2 { float4 f; unsigned long long u[2]; };

#define PACK_BCAST(dst, src) \
    asm("mov.b64 %0, {%1, %1};" : "=l"(dst) : "f"(src))
#define FFMA2(acc, a2, b2) \
    asm("fma.rn.f32x2 %0, %1, %2, %0;" : "+l"(acc) : "l"(a2), "l"(b2))
#define UNPACK2(lo, hi, src) \
    asm("mov.b64 {%0, %1}, %2;" : "=f"(lo), "=f"(hi) : "l"(src))

__global__ __launch_bounds__(256)
void fused_kernel(const float* __restrict__ h,
                  const float* __restrict__ W,
                  const float* __restrict__ b,
                  float* __restrict__ out,
                  int n_dst) {
    extern __shared__ __align__(16) char smem[];
    float* Ms = (float*)(smem + SM_MS);                                  // [64][128]
    unsigned long long (*Zs2)[ZS2_STRIDE] =
        (unsigned long long (*)[ZS2_STRIDE])(smem + SM_ZS2);             // [32][66]
    float (*Ws)[WS_STRIDE] = (float (*)[WS_STRIDE])(smem + SM_WS);       // [32][132]

    const int tid  = threadIdx.x;
    const int wi   = tid >> 5;
    const int lane = tid & 31;
    const int tx   = tid & 15;
    const int ty   = tid >> 4;
    const int row0 = blockIdx.x * GBM;

    const float4* __restrict__ h4 = (const float4*)h;

    // ---- Phase 1: gather + mean for this CTA's 64 rows (8 dsts per warp) ----
    int novf = g_ovf_n;  // broadcast L2 read; normally 0
    if (novf > MAX_OVF) novf = MAX_OVF;

#pragma unroll 1
    for (int r = 0; r < 8; r++) {
        int lm = wi * 8 + r;          // local row 0..63
        int w  = row0 + lm;
        float4 acc = make_float4(0.f, 0.f, 0.f, 0.f);
        if (w < n_dst) {
            int cnt = g_cnt[w];
            int m = cnt < CAP ? cnt : CAP;
            const int* __restrict__ bkt = g_csr + (size_t)w * CAP;
            int i = 0;
            for (; i + 8 <= m; i += 8) {
                float4 v[8];
#pragma unroll
                for (int j = 0; j < 8; j++) {
                    int s = bkt[i + j];
                    v[j] = h4[(size_t)s * 32 + lane];
                }
#pragma unroll
                for (int j = 0; j < 8; j++) {
                    acc.x += v[j].x; acc.y += v[j].y;
                    acc.z += v[j].z; acc.w += v[j].w;
                }
            }
            for (; i < m; i++) {
                int s = bkt[i];
                float4 v = h4[(size_t)s * 32 + lane];
                acc.x += v.x; acc.y += v.y; acc.z += v.z; acc.w += v.w;
            }
            if (novf > 0) {           // overflow fixup (normally skipped)
                for (int e = 0; e < novf; e++) {
                    if (g_ovf[2 * e] == w) {
                        int s = g_ovf[2 * e + 1];
                        float4 v = h4[(size_t)s * 32 + lane];
                        acc.x += v.x; acc.y += v.y; acc.z += v.z; acc.w += v.w;
                    }
                }
            }
            float inv = 1.0f / fmaxf((float)cnt, 1.0f);
            acc.x *= inv; acc.y *= inv; acc.z *= inv; acc.w *= inv;
        }
        ((float4*)(Ms + lm * DIMD))[lane] = acc;
    }
    __syncthreads();

    // ---- Phase 2: full K=256 GEMM; Z = [h rows (global) ; Ms (smem)] ----
    unsigned long long acc[4][4];
#pragma unroll
    for (int i = 0; i < 4; i++)
#pragma unroll
        for (int j = 0; j < 4; j++) acc[i][j] = 0ull;

    for (int kk = 0; kk < KDIM; kk += GBK) {
        // Z tile: 64 rows x 32 k, pre-packed broadcast pairs
#pragma unroll
        for (int i = 0; i < 2; i++) {
            int f  = tid + i * 256;
            int mm = f >> 3;
            int k4 = (f & 7) * 4;
            float4 v;
            if (kk < DIMD) {
                int row = row0 + mm;
                v = make_float4(0.f, 0.f, 0.f, 0.f);
                if (row < n_dst)
                    v = *(const float4*)(h + (size_t)row * DIMD + kk + k4);
            } else {
                v = *(const float4*)(Ms + mm * DIMD + (kk - DIMD) + k4);
            }
            unsigned long long p0, p1, p2, p3;
            PACK_BCAST(p0, v.x); PACK_BCAST(p1, v.y);
            PACK_BCAST(p2, v.z); PACK_BCAST(p3, v.w);
            Zs2[k4 + 0][mm] = p0; Zs2[k4 + 1][mm] = p1;
            Zs2[k4 + 2][mm] = p2; Zs2[k4 + 3][mm] = p3;
        }
        // W tile: 128 n x 32 k
#pragma unroll
        for (int i = 0; i < 4; i++) {
            int f  = tid + i * 256;
            int nn = f >> 3;
            int k4 = (f & 7) * 4;
            float4 v = *(const float4*)(W + (size_t)nn * KDIM + kk + k4);
            Ws[k4 + 0][nn] = v.x; Ws[k4 + 1][nn] = v.y;
            Ws[k4 + 2][nn] = v.z; Ws[k4 + 3][nn] = v.w;
        }
        __syncthreads();

#pragma unroll
        for (int k = 0; k < GBK; k++) {
            unsigned long long z2[4];
#pragma unroll
            for (int i = 0; i < 4; i++) z2[i] = Zs2[k][ty * 4 + i];
            F4U2 w0, w1;
            w0.f = *(const float4*)&Ws[k][tx * 8];
            w1.f = *(const float4*)&Ws[k][tx * 8 + 4];
#pragma unroll
            for (int i = 0; i < 4; i++) {
                FFMA2(acc[i][0], z2[i], w0.u[0]);
                FFMA2(acc[i][1], z2[i], w0.u[1]);
                FFMA2(acc[i][2], z2[i], w1.u[0]);
                FFMA2(acc[i][3], z2[i], w1.u[1]);
            }
        }
        __syncthreads();
    }

    // ---- Epilogue: bias + relu ----
    float bias[8];
#pragma unroll
    for (int j = 0; j < 8; j++) bias[j] = b[tx * 8 + j];

#pragma unroll
    for (int i = 0; i < 4; i++) {
        int row = row0 + ty * 4 + i;
        if (row < n_dst) {
            float a[8];
            UNPACK2(a[0], a[1], acc[i][0]);
            UNPACK2(a[2], a[3], acc[i][1]);
            UNPACK2(a[4], a[5], acc[i][2]);
            UNPACK2(a[6], a[7], acc[i][3]);
            float4 o0, o1;
            o0.x = fmaxf(a[0] + bias[0], 0.f);
            o0.y = fmaxf(a[1] + bias[1], 0.f);
            o0.z = fmaxf(a[2] + bias[2], 0.f);
            o0.w = fmaxf(a[3] + bias[3], 0.f);
            o1.x = fmaxf(a[4] + bias[4], 0.f);
            o1.y = fmaxf(a[5] + bias[5], 0.f);
            o1.z = fmaxf(a[6] + bias[6], 0.f);
            o1.w = fmaxf(a[7] + bias[7], 0.f);
            float* op = out + (size_t)row * OUTN + tx * 8;
            *(float4*)(op)     = o0;
            *(float4*)(op + 4) = o1;
        }
    }
}

// ---------------------------------------------------------------------------
extern "C" void kernel_launch(void* const* d_in, const int* in_sizes, int n_in,
                              void* d_out, int out_size) {
    const float* h    = (const float*)d_in[0];
    const void*  esrc = d_in[1];
    const void*  edst = d_in[2];
    const float* W    = (const float*)d_in[3];
    const float* b    = (const float*)d_in[4];
    float*       out  = (float*)d_out;

    int n_dst = out_size / OUTN;            // 20000
    if (n_dst > MAX_DST) n_dst = MAX_DST;
    int n_src = in_sizes[0] / DIMD;         // 100000
    int E     = in_sizes[1];                // 600000

    static int smem_set = 0;
    if (!smem_set) {
        cudaFuncSetAttribute(fused_kernel,
                             cudaFuncAttributeMaxDynamicSharedMemorySize, SM_TOT);
        smem_set = 1;
    }

    init_kernel<<<(n_dst + 511) / 512, 512>>>(esrc, edst, E, n_src, n_dst);

    if (E > 0)
        scatter_kernel<<<(E + 255) / 256, 256>>>(esrc, edst, E);

    fused_kernel<<<(n_dst + GBM - 1) / GBM, 256, SM_TOT>>>(h, W, b, out, n_dst);
}

// round 15
// speedup vs baseline: 1.0531x; 1.0531x over previous
#include <cuda_runtime.h>
#include <cstdint>

// ---------------------------------------------------------------------------
// MyGraphConv: out = relu([h[:n_dst] || segment_mean(h[edge_src], edge_dst)] @ W.T + b)
//
// R15 plan — 4 strictly-linear graph nodes:
//   N1 memsetAsync : zero g_cnt[0..MAX_DST] (incl. overflow counter slot)
//   N2 scatter     : 1 edge/thread bucket scatter; per-CTA parallel dtype
//                    probe on 16 fixed samples (identical verdict in all CTAs)
//   N3 gather      : 1 warp/dst, 8-way unrolled, full-occupancy (at LTS floor)
//   N4 gemm        : full K=256 (h-half from global, mean-half from g_mean),
//                    FFMA2 inner loop w/ pre-packed broadcast Z pairs,
//                    bias + relu epilogue. No fork, no g_part.
// ---------------------------------------------------------------------------

#define MAX_DST 32768
#define CAP     128
#define MAX_OVF 65536
#define DIMD    128
#define OUTN    128
#define KDIM    256

// g_cnt[MAX_DST] doubles as the overflow counter -> one contiguous memset.
__device__ int g_cnt[MAX_DST + 1];
__device__ int g_csr[(size_t)MAX_DST * CAP];
__device__ int g_ovf[2 * MAX_OVF];
__device__ __align__(16) float g_mean[(size_t)MAX_DST * DIMD];

// --- N2: bucket scatter with inline dtype probe ---------------------------------
// int64 buffers: every sampled 8B word is a small valid index. int32 buffers:
// an 8B read packs two indices -> exceeds range unless the high half is 0
// (p ~ 2e-5/sample; 16 samples -> ~1e-75 false-accept). All CTAs sample the
// SAME slots (first E/2 int64 slots: in-bounds for either dtype), so every
// CTA reaches the identical verdict.
__global__ void scatter_kernel(const void* __restrict__ esrc,
                               const void* __restrict__ edst,
                               int E, int n_src, int n_dst) {
    __shared__ int s_is64;
    if (threadIdx.x == 0) s_is64 = 1;
    __syncthreads();
    if (threadIdx.x < 16) {
        int lim = E >> 1;
        if (lim < 1) {
            if (threadIdx.x == 0) s_is64 = 0;
        } else {
            int step = (lim > 16) ? (lim / 16) : 1;
            int j = threadIdx.x * step;
            if (j < lim) {
                unsigned long long a = ((const unsigned long long*)esrc)[j];
                unsigned long long c = ((const unsigned long long*)edst)[j];
                if (a >= (unsigned long long)n_src ||
                    c >= (unsigned long long)n_dst)
                    atomicAnd(&s_is64, 0);
            }
        }
    }
    __syncthreads();
    bool is64 = (s_is64 != 0);

    int i = blockIdx.x * blockDim.x + threadIdx.x;
    if (i >= E) return;
    int s, d;
    if (is64) {
        s = (int)((const long long*)esrc)[i];
        d = (int)((const long long*)edst)[i];
    } else {
        s = ((const int*)esrc)[i];
        d = ((const int*)edst)[i];
    }
    int pos = atomicAdd(&g_cnt[d], 1);
    if (pos < CAP) {
        g_csr[(size_t)d * CAP + pos] = s;
    } else {
        int o = atomicAdd(&g_cnt[MAX_DST], 1);
        if (o < MAX_OVF) { g_ovf[2 * o] = d; g_ovf[2 * o + 1] = s; }
    }
}

// --- N3: gather + mean (1 warp/dst, fp32, 8-way unroll, inline overflow) ---------
__global__ void gather_kernel(const float* __restrict__ h, int n_dst) {
    int w    = (int)((blockIdx.x * (unsigned)blockDim.x + threadIdx.x) >> 5);
    int lane = threadIdx.x & 31;
    if (w >= n_dst) return;

    int cnt = g_cnt[w];
    int m = cnt < CAP ? cnt : CAP;
    const int* __restrict__ bkt = g_csr + (size_t)w * CAP;
    const float4* __restrict__ h4 = (const float4*)h;

    float4 acc = make_float4(0.f, 0.f, 0.f, 0.f);
    int i = 0;
    for (; i + 8 <= m; i += 8) {
        float4 v[8];
#pragma unroll
        for (int j = 0; j < 8; j++) {
            int s = bkt[i + j];
            v[j] = h4[(size_t)s * 32 + lane];
        }
#pragma unroll
        for (int j = 0; j < 8; j++) {
            acc.x += v[j].x; acc.y += v[j].y; acc.z += v[j].z; acc.w += v[j].w;
        }
    }
    for (; i < m; i++) {
        int s = bkt[i];
        float4 v = h4[(size_t)s * 32 + lane];
        acc.x += v.x; acc.y += v.y; acc.z += v.z; acc.w += v.w;
    }

    // Inline overflow fixup (normally g_cnt[MAX_DST] == 0: one broadcast read)
    int novf = g_cnt[MAX_DST];
    if (novf > 0) {
        if (novf > MAX_OVF) novf = MAX_OVF;
        for (int e = 0; e < novf; e++) {
            if (g_ovf[2 * e] == w) {
                int s = g_ovf[2 * e + 1];
                float4 v = h4[(size_t)s * 32 + lane];
                acc.x += v.x; acc.y += v.y; acc.z += v.z; acc.w += v.w;
            }
        }
    }

    float inv = 1.0f / fmaxf((float)cnt, 1.0f);
    acc.x *= inv; acc.y *= inv; acc.z *= inv; acc.w *= inv;
    ((float4*)g_mean)[(size_t)w * 32 + lane] = acc;
}

// --- N4: full K=256 GEMM + bias + relu -------------------------------------------
#define GBM 64
#define GBK 32
#define ZS2_STRIDE 66    // ulonglong stride: 64 + 2 pad
#define WS_STRIDE  132

union F4U2 { float4 f; unsigned long long u[2]; };

#define PACK_BCAST(dst, src) \
    asm("mov.b64 %0, {%1, %1};" : "=l"(dst) : "f"(src))
#define FFMA2(acc, a2, b2) \
    asm("fma.rn.f32x2 %0, %1, %2, %0;" : "+l"(acc) : "l"(a2), "l"(b2))
#define UNPACK2(lo, hi, src) \
    asm("mov.b64 {%0, %1}, %2;" : "=f"(lo), "=f"(hi) : "l"(src))

__global__ __launch_bounds__(256, 3)
void gemm_kernel(const float* __restrict__ h,
                 const float* __restrict__ W,
                 const float* __restrict__ b,
                 float* __restrict__ out,
                 int n_dst) {
    __shared__ __align__(16) unsigned long long Zs2[GBK][ZS2_STRIDE];
    __shared__ __align__(16) float Ws[GBK][WS_STRIDE];

    const int tid  = threadIdx.x;        // 0..255
    const int tx   = tid & 15;           // n group: cols tx*8 .. tx*8+7
    const int ty   = tid >> 4;           // m group: rows ty*4 .. ty*4+3
    const int row0 = blockIdx.x * GBM;

    unsigned long long acc[4][4];
#pragma unroll
    for (int i = 0; i < 4; i++)
#pragma unroll
        for (int j = 0; j < 4; j++) acc[i][j] = 0ull;

    for (int kk = 0; kk < KDIM; kk += GBK) {
        const float* __restrict__ srcZ = (kk < DIMD) ? h : g_mean;
        const int kb = kk & (DIMD - 1);

        // Z tile: 64 rows x 32 k, stored as broadcast-packed f32x2 pairs
#pragma unroll
        for (int i = 0; i < 2; i++) {
            int f  = tid + i * 256;
            int mm = f >> 3;             // 0..63
            int k4 = (f & 7) * 4;        // 0..28
            int row = row0 + mm;
            float4 v = make_float4(0.f, 0.f, 0.f, 0.f);
            if (row < n_dst)
                v = *(const float4*)(srcZ + (size_t)row * DIMD + kb + k4);
            unsigned long long p0, p1, p2, p3;
            PACK_BCAST(p0, v.x); PACK_BCAST(p1, v.y);
            PACK_BCAST(p2, v.z); PACK_BCAST(p3, v.w);
            Zs2[k4 + 0][mm] = p0; Zs2[k4 + 1][mm] = p1;
            Zs2[k4 + 2][mm] = p2; Zs2[k4 + 3][mm] = p3;
        }
        // W tile: 128 n x 32 k
#pragma unroll
        for (int i = 0; i < 4; i++) {
            int f  = tid + i * 256;
            int nn = f >> 3;             // 0..127
            int k4 = (f & 7) * 4;
            float4 v = *(const float4*)(W + (size_t)nn * KDIM + kk + k4);
            Ws[k4 + 0][nn] = v.x; Ws[k4 + 1][nn] = v.y;
            Ws[k4 + 2][nn] = v.z; Ws[k4 + 3][nn] = v.w;
        }
        __syncthreads();

#pragma unroll
        for (int k = 0; k < GBK; k++) {
            unsigned long long z2[4];
#pragma unroll
            for (int i = 0; i < 4; i++) z2[i] = Zs2[k][ty * 4 + i];
            F4U2 w0, w1;
            w0.f = *(const float4*)&Ws[k][tx * 8];
            w1.f = *(const float4*)&Ws[k][tx * 8 + 4];
#pragma unroll
            for (int i = 0; i < 4; i++) {
                FFMA2(acc[i][0], z2[i], w0.u[0]);
                FFMA2(acc[i][1], z2[i], w0.u[1]);
                FFMA2(acc[i][2], z2[i], w1.u[0]);
                FFMA2(acc[i][3], z2[i], w1.u[1]);
            }
        }
        __syncthreads();
    }

    float bias[8];
#pragma unroll
    for (int j = 0; j < 8; j++) bias[j] = b[tx * 8 + j];

#pragma unroll
    for (int i = 0; i < 4; i++) {
        int row = row0 + ty * 4 + i;
        if (row < n_dst) {
            float a[8];
            UNPACK2(a[0], a[1], acc[i][0]);
            UNPACK2(a[2], a[3], acc[i][1]);
            UNPACK2(a[4], a[5], acc[i][2]);
            UNPACK2(a[6], a[7], acc[i][3]);
            float4 o0, o1;
            o0.x = fmaxf(a[0] + bias[0], 0.f);
            o0.y = fmaxf(a[1] + bias[1], 0.f);
            o0.z = fmaxf(a[2] + bias[2], 0.f);
            o0.w = fmaxf(a[3] + bias[3], 0.f);
            o1.x = fmaxf(a[4] + bias[4], 0.f);
            o1.y = fmaxf(a[5] + bias[5], 0.f);
            o1.z = fmaxf(a[6] + bias[6], 0.f);
            o1.w = fmaxf(a[7] + bias[7], 0.f);
            float* op = out + (size_t)row * OUTN + tx * 8;
            *(float4*)(op)     = o0;
            *(float4*)(op + 4) = o1;
        }
    }
}

// ---------------------------------------------------------------------------
extern "C" void kernel_launch(void* const* d_in, const int* in_sizes, int n_in,
                              void* d_out, int out_size) {
    const float* h    = (const float*)d_in[0];
    const void*  esrc = d_in[1];
    const void*  edst = d_in[2];
    const float* W    = (const float*)d_in[3];
    const float* b    = (const float*)d_in[4];
    float*       out  = (float*)d_out;

    int n_dst = out_size / OUTN;            // 20000
    if (n_dst > MAX_DST) n_dst = MAX_DST;
    int n_src = in_sizes[0] / DIMD;         // 100000
    int E     = in_sizes[1];                // 600000

    // N1: zero counters (incl. overflow slot) via one async memset node.
    void* cnt_ptr = nullptr;
    cudaGetSymbolAddress(&cnt_ptr, g_cnt);
    cudaMemsetAsync(cnt_ptr, 0, (size_t)(MAX_DST + 1) * sizeof(int));

    // N2: scatter (with per-CTA dtype probe)
    if (E > 0)
        scatter_kernel<<<(E + 255) / 256, 256>>>(esrc, edst, E, n_src, n_dst);

    // N3: gather
    gather_kernel<<<(n_dst * 32 + 255) / 256, 256>>>(h, n_dst);

    // N4: full GEMM + bias + relu
    gemm_kernel<<<(n_dst + GBM - 1) / GBM, 256>>>(h, W, b, out, n_dst);
}

// round 16
// speedup vs baseline: 1.1665x; 1.1077x over previous
#include <cuda_runtime.h>
#include <cstdint>

// ---------------------------------------------------------------------------
// MyGraphConv: out = relu([h[:n_dst] || segment_mean(h[edge_src], edge_dst)] @ W.T + b)
//
// R16 plan — R10 structure + chunked gather/gemmB software pipeline:
//   main: memset(g_cnt) -> scatter (inline dtype probe)
//         -> gather[0,SPLIT) -> evG0 -> gather[SPLIT,n) -> wait(evA) -> gemmB1
//         -> wait(evB0)
//   s2  : wait(evFork) -> gemmA (g_part = h_dst @ W0.T, all rows) -> evA
//         -> wait(evG0) -> gemmB0 (chunk0; overlaps gather chunk1) -> evB0
//   gemmB is FMA-bound, gather is L2-bound -> they overlap cleanly.
// ---------------------------------------------------------------------------

#define MAX_DST 32768
#define CAP     128
#define MAX_OVF 65536
#define DIMD    128
#define OUTN    128
#define KDIM    256

// g_cnt[MAX_DST] doubles as the overflow counter -> one contiguous memset.
__device__ int g_cnt[MAX_DST + 1];
__device__ int g_csr[(size_t)MAX_DST * CAP];
__device__ int g_ovf[2 * MAX_OVF];
__device__ __align__(16) float g_mean[(size_t)MAX_DST * DIMD];
__device__ __align__(16) float g_part[(size_t)MAX_DST * OUTN];

// --- scatter with inline dtype probe --------------------------------------------
// int64 buffers: every sampled 8B word is a small valid index. int32 buffers:
// an 8B read packs two indices -> exceeds range unless the high half is 0
// (16 samples -> false-accept ~1e-75). All CTAs sample the SAME fixed slots
// (within the first E/2 int64 slots: in-bounds for either dtype).
__global__ void scatter_kernel(const void* __restrict__ esrc,
                               const void* __restrict__ edst,
                               int E, int n_src, int n_dst) {
    __shared__ int s_is64;
    if (threadIdx.x == 0) s_is64 = 1;
    __syncthreads();
    if (threadIdx.x < 16) {
        int lim = E >> 1;
        if (lim < 1) {
            if (threadIdx.x == 0) s_is64 = 0;
        } else {
            int step = (lim > 16) ? (lim / 16) : 1;
            int j = threadIdx.x * step;
            if (j < lim) {
                unsigned long long a = ((const unsigned long long*)esrc)[j];
                unsigned long long c = ((const unsigned long long*)edst)[j];
                if (a >= (unsigned long long)n_src ||
                    c >= (unsigned long long)n_dst)
                    atomicAnd(&s_is64, 0);
            }
        }
    }
    __syncthreads();
    bool is64 = (s_is64 != 0);

    int i = blockIdx.x * blockDim.x + threadIdx.x;
    if (i >= E) return;
    int s, d;
    if (is64) {
        s = (int)((const long long*)esrc)[i];
        d = (int)((const long long*)edst)[i];
    } else {
        s = ((const int*)esrc)[i];
        d = ((const int*)edst)[i];
    }
    int pos = atomicAdd(&g_cnt[d], 1);
    if (pos < CAP) {
        g_csr[(size_t)d * CAP + pos] = s;
    } else {
        int o = atomicAdd(&g_cnt[MAX_DST], 1);
        if (o < MAX_OVF) { g_ovf[2 * o] = d; g_ovf[2 * o + 1] = s; }
    }
}

// --- gather + mean over dst range [wbeg, wend): 1 warp/dst, 8-way unroll ---------
__global__ void gather_kernel(const float* __restrict__ h, int wbeg, int wend) {
    int w    = wbeg + (int)((blockIdx.x * (unsigned)blockDim.x + threadIdx.x) >> 5);
    int lane = threadIdx.x & 31;
    if (w >= wend) return;

    int cnt = g_cnt[w];
    int m = cnt < CAP ? cnt : CAP;
    const int* __restrict__ bkt = g_csr + (size_t)w * CAP;
    const float4* __restrict__ h4 = (const float4*)h;

    float4 acc = make_float4(0.f, 0.f, 0.f, 0.f);
    int i = 0;
    for (; i + 8 <= m; i += 8) {
        float4 v[8];
#pragma unroll
        for (int j = 0; j < 8; j++) {
            int s = bkt[i + j];
            v[j] = h4[(size_t)s * 32 + lane];
        }
#pragma unroll
        for (int j = 0; j < 8; j++) {
            acc.x += v[j].x; acc.y += v[j].y; acc.z += v[j].z; acc.w += v[j].w;
        }
    }
    for (; i < m; i++) {
        int s = bkt[i];
        float4 v = h4[(size_t)s * 32 + lane];
        acc.x += v.x; acc.y += v.y; acc.z += v.z; acc.w += v.w;
    }

    // Inline overflow fixup (normally g_cnt[MAX_DST] == 0: one broadcast read)
    int novf = g_cnt[MAX_DST];
    if (novf > 0) {
        if (novf > MAX_OVF) novf = MAX_OVF;
        for (int e = 0; e < novf; e++) {
            if (g_ovf[2 * e] == w) {
                int s = g_ovf[2 * e + 1];
                float4 v = h4[(size_t)s * 32 + lane];
                acc.x += v.x; acc.y += v.y; acc.z += v.z; acc.w += v.w;
            }
        }
    }

    float inv = 1.0f / fmaxf((float)cnt, 1.0f);
    acc.x *= inv; acc.y *= inv; acc.z *= inv; acc.w *= inv;
    ((float4*)g_mean)[(size_t)w * 32 + lane] = acc;
}

// --- GEMM halves: 64x128 tile, K=128 each, f32x2 FFMA2, pre-packed Z -------------
#define GBM 64
#define GBK 32
#define ZS2_STRIDE 66    // ulonglong stride: 64 + 2 pad
#define WS_STRIDE  132

union F4U2 { float4 f; unsigned long long u[2]; };

#define PACK_BCAST(dst, src) \
    asm("mov.b64 %0, {%1, %1};" : "=l"(dst) : "f"(src))
#define FFMA2(acc, a2, b2) \
    asm("fma.rn.f32x2 %0, %1, %2, %0;" : "+l"(acc) : "l"(a2), "l"(b2))
#define UNPACK2(lo, hi, src) \
    asm("mov.b64 {%0, %1}, %2;" : "=f"(lo), "=f"(hi) : "l"(src))

__device__ __forceinline__ void gemm_body(
    const float* __restrict__ srcZ, const float* __restrict__ W, int Wcol0,
    unsigned long long (*Zs2)[ZS2_STRIDE], float (*Ws)[WS_STRIDE],
    unsigned long long acc[4][4], int row0, int n_dst, int tid, int tx, int ty) {

    for (int kk = 0; kk < DIMD; kk += GBK) {
#pragma unroll
        for (int i = 0; i < 2; i++) {
            int f  = tid + i * 256;
            int mm = f >> 3;
            int k4 = (f & 7) * 4;
            int row = row0 + mm;
            float4 v = make_float4(0.f, 0.f, 0.f, 0.f);
            if (row < n_dst)
                v = *(const float4*)(srcZ + (size_t)row * DIMD + kk + k4);
            unsigned long long p0, p1, p2, p3;
            PACK_BCAST(p0, v.x); PACK_BCAST(p1, v.y);
            PACK_BCAST(p2, v.z); PACK_BCAST(p3, v.w);
            Zs2[k4 + 0][mm] = p0; Zs2[k4 + 1][mm] = p1;
            Zs2[k4 + 2][mm] = p2; Zs2[k4 + 3][mm] = p3;
        }
#pragma unroll
        for (int i = 0; i < 4; i++) {
            int f  = tid + i * 256;
            int nn = f >> 3;
            int k4 = (f & 7) * 4;
            float4 v = *(const float4*)(W + (size_t)nn * KDIM + Wcol0 + kk + k4);
            Ws[k4 + 0][nn] = v.x; Ws[k4 + 1][nn] = v.y;
            Ws[k4 + 2][nn] = v.z; Ws[k4 + 3][nn] = v.w;
        }
        __syncthreads();

#pragma unroll
        for (int k = 0; k < GBK; k++) {
            unsigned long long z2[4];
#pragma unroll
            for (int i = 0; i < 4; i++) z2[i] = Zs2[k][ty * 4 + i];
            F4U2 w0, w1;
            w0.f = *(const float4*)&Ws[k][tx * 8];
            w1.f = *(const float4*)&Ws[k][tx * 8 + 4];
#pragma unroll
            for (int i = 0; i < 4; i++) {
                FFMA2(acc[i][0], z2[i], w0.u[0]);
                FFMA2(acc[i][1], z2[i], w0.u[1]);
                FFMA2(acc[i][2], z2[i], w1.u[0]);
                FFMA2(acc[i][3], z2[i], w1.u[1]);
            }
        }
        __syncthreads();
    }
}

// gemmA: g_part = h_dst @ W[:, :128].T  (all rows)
__global__ __launch_bounds__(256, 3)
void gemmA_kernel(const float* __restrict__ h,
                  const float* __restrict__ W,
                  int n_dst) {
    __shared__ __align__(16) unsigned long long Zs2[GBK][ZS2_STRIDE];
    __shared__ __align__(16) float Ws[GBK][WS_STRIDE];
    const int tid  = threadIdx.x;
    const int tx   = tid & 15;
    const int ty   = tid >> 4;
    const int row0 = blockIdx.x * GBM;

    unsigned long long acc[4][4];
#pragma unroll
    for (int i = 0; i < 4; i++)
#pragma unroll
        for (int j = 0; j < 4; j++) acc[i][j] = 0ull;

    gemm_body(h, W, 0, Zs2, Ws, acc, row0, n_dst, tid, tx, ty);

#pragma unroll
    for (int i = 0; i < 4; i++) {
        int row = row0 + ty * 4 + i;
        if (row < n_dst) {
            float4 o0, o1;
            UNPACK2(o0.x, o0.y, acc[i][0]);
            UNPACK2(o0.z, o0.w, acc[i][1]);
            UNPACK2(o1.x, o1.y, acc[i][2]);
            UNPACK2(o1.z, o1.w, acc[i][3]);
            float* op = g_part + (size_t)row * OUTN + tx * 8;
            *(float4*)(op)     = o0;
            *(float4*)(op + 4) = o1;
        }
    }
}

// gemmB: out = relu(g_part + g_mean @ W[:, 128:].T + b), rows [block0*64, ...)
__global__ __launch_bounds__(256, 3)
void gemmB_kernel(const float* __restrict__ W,
                  const float* __restrict__ b,
                  float* __restrict__ out,
                  int n_dst, int block0) {
    __shared__ __align__(16) unsigned long long Zs2[GBK][ZS2_STRIDE];
    __shared__ __align__(16) float Ws[GBK][WS_STRIDE];
    const int tid  = threadIdx.x;
    const int tx   = tid & 15;
    const int ty   = tid >> 4;
    const int row0 = (block0 + blockIdx.x) * GBM;

    unsigned long long acc[4][4];
#pragma unroll
    for (int i = 0; i < 4; i++)
#pragma unroll
        for (int j = 0; j < 4; j++) acc[i][j] = 0ull;

    gemm_body(g_mean, W, DIMD, Zs2, Ws, acc, row0, n_dst, tid, tx, ty);

    float bias[8];
#pragma unroll
    for (int j = 0; j < 8; j++) bias[j] = b[tx * 8 + j];

#pragma unroll
    for (int i = 0; i < 4; i++) {
        int row = row0 + ty * 4 + i;
        if (row < n_dst) {
            float a[8];
            UNPACK2(a[0], a[1], acc[i][0]);
            UNPACK2(a[2], a[3], acc[i][1]);
            UNPACK2(a[4], a[5], acc[i][2]);
            UNPACK2(a[6], a[7], acc[i][3]);
            const float* pp = g_part + (size_t)row * OUTN + tx * 8;
            float4 p0 = *(const float4*)(pp);
            float4 p1 = *(const float4*)(pp + 4);
            float4 o0, o1;
            o0.x = fmaxf(a[0] + p0.x + bias[0], 0.f);
            o0.y = fmaxf(a[1] + p0.y + bias[1], 0.f);
            o0.z = fmaxf(a[2] + p0.z + bias[2], 0.f);
            o0.w = fmaxf(a[3] + p0.w + bias[3], 0.f);
            o1.x = fmaxf(a[4] + p1.x + bias[4], 0.f);
            o1.y = fmaxf(a[5] + p1.y + bias[5], 0.f);
            o1.z = fmaxf(a[6] + p1.z + bias[6], 0.f);
            o1.w = fmaxf(a[7] + p1.w + bias[7], 0.f);
            float* op = out + (size_t)row * OUTN + tx * 8;
            *(float4*)(op)     = o0;
            *(float4*)(op + 4) = o1;
        }
    }
}

// ---------------------------------------------------------------------------
extern "C" void kernel_launch(void* const* d_in, const int* in_sizes, int n_in,
                              void* d_out, int out_size) {
    const float* h    = (const float*)d_in[0];
    const void*  esrc = d_in[1];
    const void*  edst = d_in[2];
    const float* W    = (const float*)d_in[3];
    const float* b    = (const float*)d_in[4];
    float*       out  = (float*)d_out;

    int n_dst = out_size / OUTN;            // 20000
    if (n_dst > MAX_DST) n_dst = MAX_DST;
    int n_src = in_sizes[0] / DIMD;         // 100000
    int E     = in_sizes[1];                // 600000

    int nblocks = (n_dst + GBM - 1) / GBM;  // 313
    int blocks0 = (nblocks + 1) / 2;        // chunk0 blocks (157)
    int split   = blocks0 * GBM;            // chunk0 dst rows
    if (split > n_dst) split = n_dst;
    int blocks1 = nblocks - blocks0;

    cudaStream_t s2 = 0;
    cudaEvent_t evFork = 0, evG0 = 0, evA = 0, evB0 = 0;
    bool fork_ok =
        (cudaStreamCreateWithFlags(&s2, cudaStreamNonBlocking) == cudaSuccess) &&
        (cudaEventCreateWithFlags(&evFork, cudaEventDisableTiming) == cudaSuccess) &&
        (cudaEventCreateWithFlags(&evG0, cudaEventDisableTiming) == cudaSuccess) &&
        (cudaEventCreateWithFlags(&evA, cudaEventDisableTiming) == cudaSuccess) &&
        (cudaEventCreateWithFlags(&evB0, cudaEventDisableTiming) == cudaSuccess);

    // N1: zero counters (incl. overflow slot)
    void* cnt_ptr = nullptr;
    cudaGetSymbolAddress(&cnt_ptr, g_cnt);
    cudaMemsetAsync(cnt_ptr, 0, (size_t)(MAX_DST + 1) * sizeof(int));

    if (fork_ok) {
        cudaEventRecord(evFork, 0);
        cudaStreamWaitEvent(s2, evFork, 0);
        gemmA_kernel<<<nblocks, 256, 0, s2>>>(h, W, n_dst);   // overlaps scatter+gather0
        cudaEventRecord(evA, s2);
    }

    // main: scatter -> gather0 -> gather1
    if (E > 0)
        scatter_kernel<<<(E + 255) / 256, 256>>>(esrc, edst, E, n_src, n_dst);

    gather_kernel<<<(split * 32 + 255) / 256, 256>>>(h, 0, split);

    if (fork_ok) {
        cudaEventRecord(evG0, 0);
        cudaStreamWaitEvent(s2, evG0, 0);
        gemmB_kernel<<<blocks0, 256, 0, s2>>>(W, b, out, n_dst, 0);  // overlaps gather1
        cudaEventRecord(evB0, s2);
    }

    if (split < n_dst)
        gather_kernel<<<((n_dst - split) * 32 + 255) / 256, 256>>>(h, split, n_dst);

    if (fork_ok) {
        cudaStreamWaitEvent((cudaStream_t)0, evA, 0);
        if (blocks1 > 0)
            gemmB_kernel<<<blocks1, 256>>>(W, b, out, n_dst, blocks0);
        cudaStreamWaitEvent((cudaStream_t)0, evB0, 0);
    } else {
        gemmA_kernel<<<nblocks, 256>>>(h, W, n_dst);
        gemmB_kernel<<<nblocks, 256>>>(W, b, out, n_dst, 0);
    }
}

// round 17
// speedup vs baseline: 1.3236x; 1.1347x over previous
#include <cuda_runtime.h>
#include <cstdint>

// ---------------------------------------------------------------------------
// MyGraphConv: out = relu([h[:n_dst] || segment_mean(h[edge_src], edge_dst)] @ W.T + b)
//
// R17 plan — R10 topology (best: 97.3us) + occupancy-focused GEMM:
//   main: memset(g_cnt) -> scatter (inline dtype probe, 1 edge/thr)
//         -> gather (1 warp/dst, full grid) -> wait(evA) -> gemmB
//   s2  : wait(evFork) -> gemmA -> evA   (hidden under scatter+gather)
//   GEMM tiles: 64x64xK128 on grid (nblocks, 2)  => ~4 CTAs/SM resident
//   (R16 measured: GEMM time is set by CTAs/SM, not FLOPs.)
// ---------------------------------------------------------------------------

#define MAX_DST 32768
#define CAP     128
#define MAX_OVF 65536
#define DIMD    128
#define OUTN    128
#define KDIM    256

// g_cnt[MAX_DST] doubles as the overflow counter -> one contiguous memset.
__device__ int g_cnt[MAX_DST + 1];
__device__ int g_csr[(size_t)MAX_DST * CAP];
__device__ int g_ovf[2 * MAX_OVF];
__device__ __align__(16) float g_mean[(size_t)MAX_DST * DIMD];
__device__ __align__(16) float g_part[(size_t)MAX_DST * OUTN];

// --- scatter with inline dtype probe --------------------------------------------
// int64 buffers: every sampled 8B word is a small valid index. int32 buffers:
// an 8B read packs two indices -> exceeds range unless the high half is 0
// (16 samples -> false-accept ~1e-75). All CTAs sample the SAME fixed slots
// (within the first E/2 int64 slots: in-bounds for either dtype).
__global__ void scatter_kernel(const void* __restrict__ esrc,
                               const void* __restrict__ edst,
                               int E, int n_src, int n_dst) {
    __shared__ int s_is64;
    if (threadIdx.x == 0) s_is64 = 1;
    __syncthreads();
    if (threadIdx.x < 16) {
        int lim = E >> 1;
        if (lim < 1) {
            if (threadIdx.x == 0) s_is64 = 0;
        } else {
            int step = (lim > 16) ? (lim / 16) : 1;
            int j = threadIdx.x * step;
            if (j < lim) {
                unsigned long long a = ((const unsigned long long*)esrc)[j];
                unsigned long long c = ((const unsigned long long*)edst)[j];
                if (a >= (unsigned long long)n_src ||
                    c >= (unsigned long long)n_dst)
                    atomicAnd(&s_is64, 0);
            }
        }
    }
    __syncthreads();
    bool is64 = (s_is64 != 0);

    int i = blockIdx.x * blockDim.x + threadIdx.x;
    if (i >= E) return;
    int s, d;
    if (is64) {
        s = (int)((const long long*)esrc)[i];
        d = (int)((const long long*)edst)[i];
    } else {
        s = ((const int*)esrc)[i];
        d = ((const int*)edst)[i];
    }
    int pos = atomicAdd(&g_cnt[d], 1);
    if (pos < CAP) {
        g_csr[(size_t)d * CAP + pos] = s;
    } else {
        int o = atomicAdd(&g_cnt[MAX_DST], 1);
        if (o < MAX_OVF) { g_ovf[2 * o] = d; g_ovf[2 * o + 1] = s; }
    }
}

// --- gather + mean (1 warp/dst, fp32, 8-way unroll, inline overflow) -------------
__global__ void gather_kernel(const float* __restrict__ h, int n_dst) {
    int w    = (int)((blockIdx.x * (unsigned)blockDim.x + threadIdx.x) >> 5);
    int lane = threadIdx.x & 31;
    if (w >= n_dst) return;

    int cnt = g_cnt[w];
    int m = cnt < CAP ? cnt : CAP;
    const int* __restrict__ bkt = g_csr + (size_t)w * CAP;
    const float4* __restrict__ h4 = (const float4*)h;

    float4 acc = make_float4(0.f, 0.f, 0.f, 0.f);
    int i = 0;
    for (; i + 8 <= m; i += 8) {
        float4 v[8];
#pragma unroll
        for (int j = 0; j < 8; j++) {
            int s = bkt[i + j];
            v[j] = h4[(size_t)s * 32 + lane];
        }
#pragma unroll
        for (int j = 0; j < 8; j++) {
            acc.x += v[j].x; acc.y += v[j].y; acc.z += v[j].z; acc.w += v[j].w;
        }
    }
    for (; i < m; i++) {
        int s = bkt[i];
        float4 v = h4[(size_t)s * 32 + lane];
        acc.x += v.x; acc.y += v.y; acc.z += v.z; acc.w += v.w;
    }

    // Inline overflow fixup (normally g_cnt[MAX_DST] == 0: one broadcast read)
    int novf = g_cnt[MAX_DST];
    if (novf > 0) {
        if (novf > MAX_OVF) novf = MAX_OVF;
        for (int e = 0; e < novf; e++) {
            if (g_ovf[2 * e] == w) {
                int s = g_ovf[2 * e + 1];
                float4 v = h4[(size_t)s * 32 + lane];
                acc.x += v.x; acc.y += v.y; acc.z += v.z; acc.w += v.w;
            }
        }
    }

    float inv = 1.0f / fmaxf((float)cnt, 1.0f);
    acc.x *= inv; acc.y *= inv; acc.z *= inv; acc.w *= inv;
    ((float4*)g_mean)[(size_t)w * 32 + lane] = acc;
}

// --- GEMM: 64x64 tiles, K=128, grid (nblocks, 2), f32x2 FFMA2 --------------------
#define GBM 64
#define GBN 64
#define GBK 32
#define ZS2_STRIDE 66    // ulonglong stride: 64 + 2 pad (row = 528B, 16B-aligned)
#define WS_STRIDE  68    // float stride: 64 + 4 pad (row = 272B, 16B-aligned)

union F4U2 { float4 f; unsigned long long u[2]; };

#define PACK_BCAST(dst, src) \
    asm("mov.b64 %0, {%1, %1};" : "=l"(dst) : "f"(src))
#define FFMA2(acc, a2, b2) \
    asm("fma.rn.f32x2 %0, %1, %2, %0;" : "+l"(acc) : "l"(a2), "l"(b2))
#define UNPACK2(lo, hi, src) \
    asm("mov.b64 {%0, %1}, %2;" : "=f"(lo), "=f"(hi) : "l"(src))

// Per CTA: rows [row0, row0+64), cols [ncol0, ncol0+64) of the half-GEMM.
// 256 threads: tx = tid&15 -> 4 cols each; ty = tid>>4 -> 4 rows each.
__device__ __forceinline__ void gemm_body(
    const float* __restrict__ srcZ, const float* __restrict__ W,
    int Wcol0, int ncol0,
    unsigned long long (*Zs2)[ZS2_STRIDE], float (*Ws)[WS_STRIDE],
    unsigned long long acc[4][2], int row0, int n_dst, int tid, int tx, int ty) {

    for (int kk = 0; kk < DIMD; kk += GBK) {
        // Z tile: 64 rows x 32 k = 512 float4, 2 per thread; pre-packed pairs
#pragma unroll
        for (int i = 0; i < 2; i++) {
            int f  = tid + i * 256;
            int mm = f >> 3;             // 0..63
            int k4 = (f & 7) * 4;        // 0..28
            int row = row0 + mm;
            float4 v = make_float4(0.f, 0.f, 0.f, 0.f);
            if (row < n_dst)
                v = *(const float4*)(srcZ + (size_t)row * DIMD + kk + k4);
            unsigned long long p0, p1, p2, p3;
            PACK_BCAST(p0, v.x); PACK_BCAST(p1, v.y);
            PACK_BCAST(p2, v.z); PACK_BCAST(p3, v.w);
            Zs2[k4 + 0][mm] = p0; Zs2[k4 + 1][mm] = p1;
            Zs2[k4 + 2][mm] = p2; Zs2[k4 + 3][mm] = p3;
        }
        // W tile: 64 n x 32 k = 512 float4, 2 per thread
#pragma unroll
        for (int i = 0; i < 2; i++) {
            int f  = tid + i * 256;
            int nn = f >> 3;             // 0..63
            int k4 = (f & 7) * 4;
            float4 v = *(const float4*)(W + (size_t)(ncol0 + nn) * KDIM + Wcol0 + kk + k4);
            Ws[k4 + 0][nn] = v.x; Ws[k4 + 1][nn] = v.y;
            Ws[k4 + 2][nn] = v.z; Ws[k4 + 3][nn] = v.w;
        }
        __syncthreads();

#pragma unroll
        for (int k = 0; k < GBK; k++) {
            // 4 broadcast z pairs (two 16B LDS), 4 w values (one 16B LDS)
            ulonglong2 za = *(const ulonglong2*)&Zs2[k][ty * 4];
            ulonglong2 zb = *(const ulonglong2*)&Zs2[k][ty * 4 + 2];
            F4U2 w; w.f = *(const float4*)&Ws[k][tx * 4];
            FFMA2(acc[0][0], za.x, w.u[0]); FFMA2(acc[0][1], za.x, w.u[1]);
            FFMA2(acc[1][0], za.y, w.u[0]); FFMA2(acc[1][1], za.y, w.u[1]);
            FFMA2(acc[2][0], zb.x, w.u[0]); FFMA2(acc[2][1], zb.x, w.u[1]);
            FFMA2(acc[3][0], zb.y, w.u[0]); FFMA2(acc[3][1], zb.y, w.u[1]);
        }
        __syncthreads();
    }
}

// gemmA: g_part[:, ncol] = h_dst @ W[ncol, :128].T
__global__ __launch_bounds__(256, 4)
void gemmA_kernel(const float* __restrict__ h,
                  const float* __restrict__ W,
                  int n_dst) {
    __shared__ __align__(16) unsigned long long Zs2[GBK][ZS2_STRIDE];
    __shared__ __align__(16) float Ws[GBK][WS_STRIDE];
    const int tid  = threadIdx.x;
    const int tx   = tid & 15;           // 16 col groups x 4 cols
    const int ty   = tid >> 4;           // 16 row groups x 4 rows
    const int row0 = blockIdx.x * GBM;
    const int ncol0 = blockIdx.y * GBN;

    unsigned long long acc[4][2];
#pragma unroll
    for (int i = 0; i < 4; i++) { acc[i][0] = 0ull; acc[i][1] = 0ull; }

    gemm_body(h, W, 0, ncol0, Zs2, Ws, acc, row0, n_dst, tid, tx, ty);

#pragma unroll
    for (int i = 0; i < 4; i++) {
        int row = row0 + ty * 4 + i;
        if (row < n_dst) {
            float4 o;
            UNPACK2(o.x, o.y, acc[i][0]);
            UNPACK2(o.z, o.w, acc[i][1]);
            *(float4*)(g_part + (size_t)row * OUTN + ncol0 + tx * 4) = o;
        }
    }
}

// gemmB: out[:, ncol] = relu(g_part[:, ncol] + g_mean @ W[ncol, 128:].T + b[ncol])
__global__ __launch_bounds__(256, 4)
void gemmB_kernel(const float* __restrict__ W,
                  const float* __restrict__ b,
                  float* __restrict__ out,
                  int n_dst) {
    __shared__ __align__(16) unsigned long long Zs2[GBK][ZS2_STRIDE];
    __shared__ __align__(16) float Ws[GBK][WS_STRIDE];
    const int tid  = threadIdx.x;
    const int tx   = tid & 15;
    const int ty   = tid >> 4;
    const int row0 = blockIdx.x * GBM;
    const int ncol0 = blockIdx.y * GBN;

    unsigned long long acc[4][2];
#pragma unroll
    for (int i = 0; i < 4; i++) { acc[i][0] = 0ull; acc[i][1] = 0ull; }

    gemm_body(g_mean, W, DIMD, ncol0, Zs2, Ws, acc, row0, n_dst, tid, tx, ty);

    float4 bias = *(const float4*)(b + ncol0 + tx * 4);

#pragma unroll
    for (int i = 0; i < 4; i++) {
        int row = row0 + ty * 4 + i;
        if (row < n_dst) {
            float a0, a1, a2, a3;
            UNPACK2(a0, a1, acc[i][0]);
            UNPACK2(a2, a3, acc[i][1]);
            float4 p = *(const float4*)(g_part + (size_t)row * OUTN + ncol0 + tx * 4);
            float4 o;
            o.x = fmaxf(a0 + p.x + bias.x, 0.f);
            o.y = fmaxf(a1 + p.y + bias.y, 0.f);
            o.z = fmaxf(a2 + p.z + bias.z, 0.f);
            o.w = fmaxf(a3 + p.w + bias.w, 0.f);
            *(float4*)(out + (size_t)row * OUTN + ncol0 + tx * 4) = o;
        }
    }
}

// ---------------------------------------------------------------------------
extern "C" void kernel_launch(void* const* d_in, const int* in_sizes, int n_in,
                              void* d_out, int out_size) {
    const float* h    = (const float*)d_in[0];
    const void*  esrc = d_in[1];
    const void*  edst = d_in[2];
    const float* W    = (const float*)d_in[3];
    const float* b    = (const float*)d_in[4];
    float*       out  = (float*)d_out;

    int n_dst = out_size / OUTN;            // 20000
    if (n_dst > MAX_DST) n_dst = MAX_DST;
    int n_src = in_sizes[0] / DIMD;         // 100000
    int E     = in_sizes[1];                // 600000

    int nblocks = (n_dst + GBM - 1) / GBM;  // 313
    dim3 ggrid(nblocks, OUTN / GBN);        // (313, 2) = 626 CTAs

    cudaStream_t s2 = 0;
    cudaEvent_t evFork = 0, evA = 0;
    bool fork_ok =
        (cudaStreamCreateWithFlags(&s2, cudaStreamNonBlocking) == cudaSuccess) &&
        (cudaEventCreateWithFlags(&evFork, cudaEventDisableTiming) == cudaSuccess) &&
        (cudaEventCreateWithFlags(&evA, cudaEventDisableTiming) == cudaSuccess);

    // N1: zero counters (incl. overflow slot)
    void* cnt_ptr = nullptr;
    cudaGetSymbolAddress(&cnt_ptr, g_cnt);
    cudaMemsetAsync(cnt_ptr, 0, (size_t)(MAX_DST + 1) * sizeof(int));

    if (fork_ok) {
        cudaEventRecord(evFork, 0);
        cudaStreamWaitEvent(s2, evFork, 0);
        gemmA_kernel<<<ggrid, 256, 0, s2>>>(h, W, n_dst);  // hidden under scatter+gather
        cudaEventRecord(evA, s2);
    }

    // main: scatter -> gather
    if (E > 0)
        scatter_kernel<<<(E + 255) / 256, 256>>>(esrc, edst, E, n_src, n_dst);

    gather_kernel<<<(n_dst * 32 + 255) / 256, 256>>>(h, n_dst);

    if (fork_ok) {
        cudaStreamWaitEvent((cudaStream_t)0, evA, 0);
    } else {
        gemmA_kernel<<<ggrid, 256>>>(h, W, n_dst);
    }

    gemmB_kernel<<<ggrid, 256>>>(W, b, out, n_dst);
}